// round 8
// baseline (speedup 1.0000x reference)
#include <cuda_runtime.h>
#include <cuda_fp16.h>
#include <cstdint>

// Batch Conv1D, implicit-im2col GEMM on mma.sync (HMMA fp16/fp32 accum).
// Round 8: 64x64 warp tiles (halves LDSM B/MAC -> L1 off the critical path)
// + 4-stage cp.async pipeline (covers DRAM latency; R7 exposed it with 2 stages).
// x pre-converted to fp16 (xconv, 56us @ 82% DRAM roofline). Calibration:
// HMMA peak ~1080 MAC/cyc/SM -> ideal GEMM ~170us; R3/R5 were L1-LDSM-bound,
// R7 latency-bound. This round removes both.

namespace {

constexpr int LOUT = 1022;
constexpr int NIT  = 24;                  // 768 k / 32
constexpr int NTHREADS = 128;
constexpr int STAGES = 4;

constexpr int A_STRIDE = 80;              // 32 fp16 (64B) + 16B pad
constexpr int A_BYTES  = 128 * A_STRIDE;  // 10240
constexpr int B_STRIDE = 272;             // 128 fp16 (256B) + 16B pad
constexpr int B_BYTES  = 32 * B_STRIDE;   // 8704

constexpr int OFF_A = 0;                              // STAGES * A_BYTES = 40960
constexpr int OFF_B = STAGES * A_BYTES;
constexpr int SMEM_TOTAL = OFF_B + STAGES * B_BYTES;  // 75776

constexpr size_t X_ELEMS = 256u * 1024u * 256u;

__device__ __half g_wf16[768 * 256];
__device__ __half g_xh[X_ELEMS + 1024];   // +pad: rows 1022/1023 im2col overrun

// ---------------- PTX helpers ----------------

__device__ __forceinline__ uint32_t smem_u32(const void* p) {
    return (uint32_t)__cvta_generic_to_shared(p);
}
__device__ __forceinline__ void cp16(uint32_t dst, const void* src) {
    asm volatile("cp.async.cg.shared.global [%0], [%1], 16;" :: "r"(dst), "l"(src));
}
__device__ __forceinline__ void cp_commit() {
    asm volatile("cp.async.commit_group;" ::: "memory");
}
__device__ __forceinline__ void cp_wait2() {
    asm volatile("cp.async.wait_group 2;" ::: "memory");
}
__device__ __forceinline__ void cp_wait0() {
    asm volatile("cp.async.wait_group 0;" ::: "memory");
}
__device__ __forceinline__ void ldsm4(uint32_t (&r)[4], uint32_t addr) {
    asm volatile("ldmatrix.sync.aligned.m8n8.x4.shared.b16 {%0,%1,%2,%3}, [%4];"
                 : "=r"(r[0]), "=r"(r[1]), "=r"(r[2]), "=r"(r[3]) : "r"(addr));
}
__device__ __forceinline__ void ldsm4t(uint32_t (&r)[4], uint32_t addr) {
    asm volatile("ldmatrix.sync.aligned.m8n8.x4.trans.shared.b16 {%0,%1,%2,%3}, [%4];"
                 : "=r"(r[0]), "=r"(r[1]), "=r"(r[2]), "=r"(r[3]) : "r"(addr));
}
__device__ __forceinline__ void mma16816(float (&c)[4], const uint32_t (&a)[4],
                                         uint32_t b0, uint32_t b1) {
    asm volatile(
        "mma.sync.aligned.m16n8k16.row.col.f32.f16.f16.f32 "
        "{%0,%1,%2,%3}, {%4,%5,%6,%7}, {%8,%9}, {%0,%1,%2,%3};"
        : "+f"(c[0]), "+f"(c[1]), "+f"(c[2]), "+f"(c[3])
        : "r"(a[0]), "r"(a[1]), "r"(a[2]), "r"(a[3]), "r"(b0), "r"(b1));
}

// ---------------- pre-passes ----------------

__global__ void xconv_kernel(const float* __restrict__ x) {
    size_t i = (size_t)blockIdx.x * 256 + threadIdx.x;   // one uint4 (8 fp16)/thread
    const float4 v0 = *(const float4*)(x + i * 8);
    const float4 v1 = *(const float4*)(x + i * 8 + 4);
    __half2 h0 = __floats2half2_rn(v0.x, v0.y);
    __half2 h1 = __floats2half2_rn(v0.z, v0.w);
    __half2 h2 = __floats2half2_rn(v1.x, v1.y);
    __half2 h3 = __floats2half2_rn(v1.z, v1.w);
    uint4 p;
    p.x = *(uint32_t*)&h0; p.y = *(uint32_t*)&h1;
    p.z = *(uint32_t*)&h2; p.w = *(uint32_t*)&h3;
    *(uint4*)(g_xh + i * 8) = p;
}

__global__ void wconv_kernel(const float* __restrict__ W) {
    int i = blockIdx.x * 256 + threadIdx.x;
    g_wf16[i] = __float2half_rn(W[i]);
}

// ---------------- main GEMM ----------------

__global__ __launch_bounds__(NTHREADS, 2)
void conv1d_hmma_kernel(const float* __restrict__ bias, float* __restrict__ out)
{
    extern __shared__ __align__(128) uint8_t smem[];
    const uint32_t sm = smem_u32(smem);

    const int tid  = threadIdx.x;
    const int wid  = tid >> 5;
    const int lane = tid & 31;

    const int f0  = blockIdx.x * 128;
    const int l0  = blockIdx.y * 128;
    const int img = blockIdx.z;

    const __half* xb = g_xh + (size_t)img * (1024 * 256);
    float*        ob = out  + (size_t)img * (LOUT * 256);

    // 2x2 warp grid, 64x64 warp tiles
    const int wm = (wid >> 1) * 64;
    const int wn = (wid & 1) * 64;

    // ldmatrix lane bases
    const uint32_t a_lane = (uint32_t)(wm + (lane & 15)) * A_STRIDE + (lane >> 4) * 16;
    const uint32_t b_lane = (uint32_t)(lane & 15) * B_STRIDE
                          + (uint32_t)(wn + (lane >> 4) * 8) * 2;

    // ---- staging: one 32-k slab per stage ----
    // A: 128 rows x 32 fp16 (64B/row); thread = one row, 4 cp16.
    const __half* a_src0 = xb + (size_t)(l0 + tid) * 256;
    // B: 32 k-rows x 128 feats; thread (tid>>2)=k-row, (tid&3)=32-feat group.
    const __half* b_src0 = g_wf16 + (size_t)(tid >> 2) * 256 + f0 + (tid & 3) * 32;

    auto stage = [&](int t) {
        const int buf = t & (STAGES - 1);
        const __half* as = a_src0 + t * 32;
        const uint32_t ad = sm + OFF_A + buf * A_BYTES + (uint32_t)tid * A_STRIDE;
        cp16(ad,      as);
        cp16(ad + 16, as + 8);
        cp16(ad + 32, as + 16);
        cp16(ad + 48, as + 24);
        const __half* bs = b_src0 + (size_t)t * 32 * 256;
        const uint32_t bd = sm + OFF_B + buf * B_BYTES
                          + (uint32_t)(tid >> 2) * B_STRIDE + (tid & 3) * 64;
        cp16(bd,      bs);
        cp16(bd + 16, bs + 8);
        cp16(bd + 32, bs + 16);
        cp16(bd + 48, bs + 24);
        cp_commit();
    };

    float acc[4][8][4];
    #pragma unroll
    for (int mt = 0; mt < 4; ++mt)
        #pragma unroll
        for (int nt = 0; nt < 8; ++nt)
            #pragma unroll
            for (int q = 0; q < 4; ++q)
                acc[mt][nt][q] = 0.f;

    // ---- prologue: fill 3 stages ----
    stage(0);
    stage(1);
    stage(2);

    for (int t = 0; t < NIT; ++t) {
        cp_wait2();                 // stage t landed (committed >= 3 groups ago)
        __syncthreads();            // also: everyone done reading buf (t-1)%4

        if (t + 3 < NIT) stage(t + 3);   // overwrite buf (t-1)%4, flies under MMAs

        const uint32_t sA = sm + OFF_A + (t & (STAGES - 1)) * A_BYTES;
        const uint32_t sB = sm + OFF_B + (t & (STAGES - 1)) * B_BYTES;

        // frags for ks=0
        uint32_t af[2][4][4], bf[2][4][4];
        #pragma unroll
        for (int mt = 0; mt < 4; ++mt)
            ldsm4(af[0][mt], sA + a_lane + mt * (16 * A_STRIDE));
        #pragma unroll
        for (int n2 = 0; n2 < 4; ++n2)
            ldsm4t(bf[0][n2], sB + b_lane + n2 * 32);

        #pragma unroll
        for (int ks = 0; ks < 2; ++ks) {
            if (ks == 0) {          // prefetch ks=1 frags under ks=0 MMAs
                #pragma unroll
                for (int mt = 0; mt < 4; ++mt)
                    ldsm4(af[1][mt], sA + a_lane + mt * (16 * A_STRIDE) + 32);
                #pragma unroll
                for (int n2 = 0; n2 < 4; ++n2)
                    ldsm4t(bf[1][n2], sB + b_lane + 16 * B_STRIDE + n2 * 32);
            }
            #pragma unroll
            for (int mt = 0; mt < 4; ++mt)
                #pragma unroll
                for (int n2 = 0; n2 < 4; ++n2) {
                    mma16816(acc[mt][2 * n2],     af[ks][mt], bf[ks][n2][0], bf[ks][n2][1]);
                    mma16816(acc[mt][2 * n2 + 1], af[ks][mt], bf[ks][n2][2], bf[ks][n2][3]);
                }
        }
    }

    // ---- epilogue: bias + guarded store from registers ----
    const int g  = lane >> 2;
    const int tq = lane & 3;
    #pragma unroll
    for (int nt = 0; nt < 8; ++nt) {
        const int col = f0 + wn + nt * 8 + tq * 2;
        const float b0 = __ldg(bias + col);
        const float b1 = __ldg(bias + col + 1);
        #pragma unroll
        for (int mt = 0; mt < 4; ++mt) {
            const int r = l0 + wm + mt * 16 + g;
            if (r < LOUT) {
                float2 v = make_float2(acc[mt][nt][0] + b0, acc[mt][nt][1] + b1);
                *(float2*)(ob + (size_t)r * 256 + col) = v;
            }
            if (r + 8 < LOUT) {
                float2 v = make_float2(acc[mt][nt][2] + b0, acc[mt][nt][3] + b1);
                *(float2*)(ob + (size_t)(r + 8) * 256 + col) = v;
            }
        }
    }
}

}  // namespace

extern "C" void kernel_launch(void* const* d_in, const int* in_sizes, int n_in,
                              void* d_out, int out_size)
{
    const float* x  = (const float*)d_in[0];   // [8,32,1024,256]
    const float* w  = (const float*)d_in[1];   // [3,256,256]
    const float* b  = (const float*)d_in[2];   // [256]
    float* out      = (float*)d_out;           // [8,32,1022,256]

    xconv_kernel<<<(int)(X_ELEMS / 8 / 256), 256>>>(x);  // x fp32 -> fp16
    wconv_kernel<<<768, 256>>>(w);                       // W fp32 -> fp16

    cudaFuncSetAttribute(conv1d_hmma_kernel,
                         cudaFuncAttributeMaxDynamicSharedMemorySize, SMEM_TOTAL);

    dim3 grid(2, 8, 256);                      // f-tiles, m-tiles, images
    conv1d_hmma_kernel<<<grid, NTHREADS, SMEM_TOTAL>>>(b, out);
}